// round 2
// baseline (speedup 1.0000x reference)
#include <cuda_runtime.h>
#include <math.h>

#define N0 2048
#define N1 1024
#define DP0 12              // 3x3 row padded to 12 floats (48B, 16B-aligned)
#define DP1 28              // 5x5 row padded to 28 floats (112B, 16B-aligned)
#define NB0 (N0 / 16)       // 128 tiles
#define NB1 (N1 / 16)       // 64 tiles
#define NTRI0 (NB0 * (NB0 + 1) / 2)   // 8256
#define NTRI1 (NB1 * (NB1 + 1) / 2)   // 2080
#define GRID_PAIR (NTRI0 + NTRI1)     // 10336

// Scratch (allocation-free rule: __device__ globals)
__device__ float  g_kn0[N0 * DP0];
__device__ float  g_inv0[N0 * DP0];
__device__ float  g_kn1[N1 * DP1];
__device__ float  g_inv1[N1 * DP1];
__device__ double g_acc0;
__device__ double g_acc1;
__device__ unsigned g_count;

// ---------------------------------------------------------------------------
// Prep (both layers in one launch): normalize + invert, write padded rows.
// Blocks 0..7  -> layer 0 (2048 threads), blocks 8..11 -> layer 1 (1024).
// ---------------------------------------------------------------------------
__global__ void prep_kernel(const float* __restrict__ in0,
                            const float* __restrict__ in1) {
    int gtid = blockIdx.x * 256 + threadIdx.x;
    if (gtid == 0) { g_acc0 = 0.0; g_acc1 = 0.0; g_count = 0u; }

    if (blockIdx.x < 8) {
        int i = gtid;                       // 0..2047
        float a[9];
        float ss = 0.f;
#pragma unroll
        for (int k = 0; k < 9; k++) { a[k] = in0[i * 9 + k]; ss += a[k] * a[k]; }
        float inv_n = 1.0f / (sqrtf(ss) + 1e-8f);
#pragma unroll
        for (int k = 0; k < 9; k++) a[k] *= inv_n;

        float c00 = a[4] * a[8] - a[5] * a[7];
        float c01 = a[5] * a[6] - a[3] * a[8];
        float c02 = a[3] * a[7] - a[4] * a[6];
        float det = a[0] * c00 + a[1] * c01 + a[2] * c02;
        float id  = 1.0f / det;

        float v[9];
        v[0] = c00 * id;
        v[1] = (a[2] * a[7] - a[1] * a[8]) * id;
        v[2] = (a[1] * a[5] - a[2] * a[4]) * id;
        v[3] = c01 * id;
        v[4] = (a[0] * a[8] - a[2] * a[6]) * id;
        v[5] = (a[2] * a[3] - a[0] * a[5]) * id;
        v[6] = c02 * id;
        v[7] = (a[1] * a[6] - a[0] * a[7]) * id;
        v[8] = (a[0] * a[4] - a[1] * a[3]) * id;

#pragma unroll
        for (int k = 0; k < 9; k++) {
            g_kn0[i * DP0 + k]  = a[k];
            g_inv0[i * DP0 + k] = v[k];
        }
        // fill padding so float4 loads never touch NaN-poisoned garbage patterns
#pragma unroll
        for (int k = 9; k < DP0; k++) { g_kn0[i * DP0 + k] = 0.f; g_inv0[i * DP0 + k] = 0.f; }
    } else {
        int i = gtid - 2048;                // 0..1023
        float m[5][10];
        float ss = 0.f;
        for (int r = 0; r < 5; r++)
            for (int c = 0; c < 5; c++) {
                float x = in1[i * 25 + r * 5 + c];
                m[r][c] = x;
                ss += x * x;
                m[r][c + 5] = (r == c) ? 1.0f : 0.0f;
            }
        float inv_n = 1.0f / (sqrtf(ss) + 1e-8f);
        for (int r = 0; r < 5; r++)
            for (int c = 0; c < 5; c++) {
                m[r][c] *= inv_n;
                g_kn1[i * DP1 + r * 5 + c] = m[r][c];
            }

        for (int col = 0; col < 5; col++) {
            int p = col;
            float best = fabsf(m[col][col]);
            for (int r = col + 1; r < 5; r++) {
                float v = fabsf(m[r][col]);
                if (v > best) { best = v; p = r; }
            }
            if (p != col) {
                for (int c = 0; c < 10; c++) {
                    float t = m[col][c]; m[col][c] = m[p][c]; m[p][c] = t;
                }
            }
            float piv = 1.0f / m[col][col];
            for (int c = col; c < 10; c++) m[col][c] *= piv;
            for (int r = 0; r < 5; r++) {
                if (r == col) continue;
                float f = m[r][col];
                for (int c = col; c < 10; c++) m[r][c] -= f * m[col][c];
            }
        }

        for (int r = 0; r < 5; r++)
            for (int c = 0; c < 5; c++)
                g_inv1[i * DP1 + r * 5 + c] = m[r][c + 5];
#pragma unroll
        for (int k = 25; k < DP1; k++) { g_kn1[i * DP1 + k] = 0.f; g_inv1[i * DP1 + k] = 0.f; }
    }
}

// ---------------------------------------------------------------------------
// Triangular tile decode: t -> (by, bx), by >= bx
// ---------------------------------------------------------------------------
__device__ __forceinline__ void tri_decode(int t, int& by, int& bx) {
    float f = sqrtf(8.0f * (float)t + 1.0f);
    int r = (int)((f - 1.0f) * 0.5f);
    while ((r + 1) * (r + 2) / 2 <= t) r++;
    while (r * (r + 1) / 2 > t) r--;
    by = r;
    bx = t - r * (r + 1) / 2;
}

// ---------------------------------------------------------------------------
// Per-layer pair body: 16x16 tile, register-resident DxD matmul.
// ---------------------------------------------------------------------------
template <int LAYER>
__device__ __forceinline__ float pair_body(int t, float* smem) {
    constexpr int D  = LAYER ? 5 : 3;
    constexpr int DP = LAYER ? DP1 : DP0;
    constexpr int F4 = DP / 4;                   // 7 or 3 float4 per row
    const float* kn  = LAYER ? g_kn1  : g_kn0;
    const float* inv = LAYER ? g_inv1 : g_inv0;

    int by, bx;
    tri_decode(t, by, bx);
    int i0 = by * 16, j0 = bx * 16;
    int tid = threadIdx.x;

    float4* s4 = (float4*)smem;
    const float4* inv4 = (const float4*)inv;
    const float4* kn4  = (const float4*)kn;
    const int nf4 = 16 * F4;

    for (int e = tid; e < 2 * nf4; e += 256) {
        bool w  = e >= nf4;
        int idx = w ? e - nf4 : e;
        int row = idx / F4;
        int comp = idx - row * F4;
        s4[e] = w ? kn4[(j0 + row) * F4 + comp] : inv4[(i0 + row) * F4 + comp];
    }
    __syncthreads();

    int tx = tid & 15, ty = tid >> 4;
    float val = 0.0f;
    if (i0 + ty > j0 + tx) {
        float ri[4 * F4], rj[4 * F4];
#pragma unroll
        for (int c = 0; c < F4; c++) {
            float4 v = s4[ty * F4 + c];
            ri[4 * c] = v.x; ri[4 * c + 1] = v.y; ri[4 * c + 2] = v.z; ri[4 * c + 3] = v.w;
            float4 u = s4[nf4 + tx * F4 + c];
            rj[4 * c] = u.x; rj[4 * c + 1] = u.y; rj[4 * c + 2] = u.z; rj[4 * c + 3] = u.w;
        }
        float s = 0.0f;
#pragma unroll
        for (int r = 0; r < D; r++) {
#pragma unroll
            for (int c = 0; c < D; c++) {
                float acc = (r == c) ? -1.0f : 0.0f;
#pragma unroll
                for (int k = 0; k < D; k++)
                    acc = fmaf(ri[r * D + k], rj[k * D + c], acc);
                s = fmaf(acc, acc, s);
            }
        }
        val = fmaxf(0.0f, 1.0f - sqrtf(s));
    }
    return val;
}

// ---------------------------------------------------------------------------
// Combined pair kernel (both layers, one grid) + in-kernel finalize.
// ---------------------------------------------------------------------------
__global__ __launch_bounds__(256, 3) void pair_all_kernel(float* __restrict__ out) {
    __shared__ float smem[2 * 16 * DP1];   // 3.5 KB, both layers fit

    int b = blockIdx.x;
    float val;
    bool layer1 = (b >= NTRI0);
    if (!layer1) val = pair_body<0>(b, smem);
    else         val = pair_body<1>(b - NTRI0, smem);

    // warp reduce
#pragma unroll
    for (int o = 16; o > 0; o >>= 1)
        val += __shfl_down_sync(0xffffffffu, val, o);

    __syncthreads();   // smem reads complete before reuse
    int tid = threadIdx.x;
    if ((tid & 31) == 0) smem[tid >> 5] = val;
    __syncthreads();

    if (tid == 0) {
        float s = 0.0f;
#pragma unroll
        for (int w = 0; w < 8; w++) s += smem[w];
        if (s != 0.0f)
            atomicAdd(layer1 ? &g_acc1 : &g_acc0, (double)s);
        __threadfence();
        unsigned done = atomicAdd(&g_count, 1u) + 1u;
        if (done == (unsigned)GRID_PAIR) {
            double a0 = atomicAdd(&g_acc0, 0.0);   // coherent read
            double a1 = atomicAdd(&g_acc1, 0.0);
            double l0 = 2.0 * a0 / ((double)N0 * (double)(N0 - 1));
            double l1 = 2.0 * a1 / ((double)N1 * (double)(N1 - 1));
            out[0] = (float)(0.5 * (l0 + l1));
        }
    }
}

extern "C" void kernel_launch(void* const* d_in, const int* in_sizes, int n_in,
                              void* d_out, int out_size) {
    const float* k0 = (const float*)d_in[0];
    const float* k1 = (const float*)d_in[1];
    float* out = (float*)d_out;

    prep_kernel<<<12, 256>>>(k0, k1);
    pair_all_kernel<<<GRID_PAIR, 256>>>(out);
}

// round 3
// speedup vs baseline: 1.7575x; 1.7575x over previous
#include <cuda_runtime.h>
#include <math.h>

#define N0 2048
#define N1 1024
#define K0 20               // 9 (A) + 9 (G) + 2 pad
#define K1 52               // 25 (A) + 25 (G) + 2 pad
#define K0_4 (K0 / 4)
#define K1_4 (K1 / 4)
#define NBT0 (N0 / 64)      // 32 tiles per side
#define NBT1 (N1 / 64)      // 16 tiles per side
#define NTRI0 (NBT0 * (NBT0 + 1) / 2)   // 528
#define NTRI1 (NBT1 * (NBT1 + 1) / 2)   // 136
#define GRID_PAIR (NTRI0 + NTRI1)       // 664

// Scratch (allocation-free rule: __device__ globals)
// U row = [A row-major, G=A^T A row-major, pad0]
// V row = [-2*B^T row-major, H=B B^T row-major, pad0]
// diff^2(i,j) = D + dot(U[i], V[j])
__device__ float  g_U0[N0 * K0];
__device__ float  g_V0[N0 * K0];
__device__ float  g_U1[N1 * K1];
__device__ float  g_V1[N1 * K1];
__device__ double g_acc0;
__device__ double g_acc1;
__device__ unsigned g_count;

// ---------------------------------------------------------------------------
// Prep: normalize, invert, build U/V rows.  Blocks 0..7 layer0, 8..11 layer1.
// ---------------------------------------------------------------------------
__global__ void prep_kernel(const float* __restrict__ in0,
                            const float* __restrict__ in1) {
    int gtid = blockIdx.x * 256 + threadIdx.x;
    if (gtid == 0) { g_acc0 = 0.0; g_acc1 = 0.0; g_count = 0u; }

    if (blockIdx.x < 8) {
        // ---------------- layer 0: 3x3 ----------------
        int i = gtid;
        float a[9];
        float ss = 0.f;
#pragma unroll
        for (int k = 0; k < 9; k++) { a[k] = in0[i * 9 + k]; ss += a[k] * a[k]; }
        float inv_n = 1.0f / (sqrtf(ss) + 1e-8f);
#pragma unroll
        for (int k = 0; k < 9; k++) a[k] *= inv_n;

        float c00 = a[4] * a[8] - a[5] * a[7];
        float c01 = a[5] * a[6] - a[3] * a[8];
        float c02 = a[3] * a[7] - a[4] * a[6];
        float det = a[0] * c00 + a[1] * c01 + a[2] * c02;
        float id  = 1.0f / det;

        float v[9];
        v[0] = c00 * id;
        v[1] = (a[2] * a[7] - a[1] * a[8]) * id;
        v[2] = (a[1] * a[5] - a[2] * a[4]) * id;
        v[3] = c01 * id;
        v[4] = (a[0] * a[8] - a[2] * a[6]) * id;
        v[5] = (a[2] * a[3] - a[0] * a[5]) * id;
        v[6] = c02 * id;
        v[7] = (a[1] * a[6] - a[0] * a[7]) * id;
        v[8] = (a[0] * a[4] - a[1] * a[3]) * id;

        float* U = &g_U0[i * K0];
        float* V = &g_V0[i * K0];
#pragma unroll
        for (int k = 0; k < 9; k++) U[k] = v[k];
        // G = A^T A  (A = v)
#pragma unroll
        for (int r = 0; r < 3; r++)
#pragma unroll
            for (int c = 0; c < 3; c++) {
                float s = 0.f;
#pragma unroll
                for (int k = 0; k < 3; k++) s += v[k * 3 + r] * v[k * 3 + c];
                U[9 + r * 3 + c] = s;
            }
        // -2 * B^T  (B = a):  V[r*3+k] = -2*a[k*3+r]
#pragma unroll
        for (int r = 0; r < 3; r++)
#pragma unroll
            for (int k = 0; k < 3; k++) V[r * 3 + k] = -2.0f * a[k * 3 + r];
        // H = B B^T
#pragma unroll
        for (int r = 0; r < 3; r++)
#pragma unroll
            for (int c = 0; c < 3; c++) {
                float s = 0.f;
#pragma unroll
                for (int k = 0; k < 3; k++) s += a[r * 3 + k] * a[c * 3 + k];
                V[9 + r * 3 + c] = s;
            }
#pragma unroll
        for (int k = 18; k < K0; k++) { U[k] = 0.f; V[k] = 0.f; }
    } else {
        // ---------------- layer 1: 5x5, register-resident pivoted GJ -------
        int i = gtid - 2048;
        float m[5][10];
        float b[25];
        float ss = 0.f;
#pragma unroll
        for (int r = 0; r < 5; r++)
#pragma unroll
            for (int c = 0; c < 5; c++) {
                float x = in1[i * 25 + r * 5 + c];
                m[r][c] = x; ss += x * x;
                m[r][c + 5] = (r == c) ? 1.0f : 0.0f;
            }
        float inv_n = 1.0f / (sqrtf(ss) + 1e-8f);
#pragma unroll
        for (int r = 0; r < 5; r++)
#pragma unroll
            for (int c = 0; c < 5; c++) { m[r][c] *= inv_n; b[r * 5 + c] = m[r][c]; }

#pragma unroll
        for (int col = 0; col < 5; col++) {
            // bubble-max partial pivoting, fully static (predicated swaps)
#pragma unroll
            for (int r2 = 0; r2 < 5; r2++) {
                if (r2 > col) {
                    bool sw = fabsf(m[r2][col]) > fabsf(m[col][col]);
#pragma unroll
                    for (int c = 0; c < 10; c++) {
                        float x = m[col][c], y = m[r2][c];
                        m[col][c] = sw ? y : x;
                        m[r2][c]  = sw ? x : y;
                    }
                }
            }
            float piv = 1.0f / m[col][col];
#pragma unroll
            for (int c = 0; c < 10; c++) m[col][c] *= piv;
#pragma unroll
            for (int r = 0; r < 5; r++) {
                if (r == col) continue;
                float f = m[r][col];
#pragma unroll
                for (int c = 0; c < 10; c++) m[r][c] = fmaf(-f, m[col][c], m[r][c]);
            }
        }

        float v[25];
#pragma unroll
        for (int r = 0; r < 5; r++)
#pragma unroll
            for (int c = 0; c < 5; c++) v[r * 5 + c] = m[r][c + 5];

        float* U = &g_U1[i * K1];
        float* V = &g_V1[i * K1];
#pragma unroll
        for (int k = 0; k < 25; k++) U[k] = v[k];
#pragma unroll
        for (int r = 0; r < 5; r++)
#pragma unroll
            for (int c = 0; c < 5; c++) {
                float s = 0.f;
#pragma unroll
                for (int k = 0; k < 5; k++) s += v[k * 5 + r] * v[k * 5 + c];
                U[25 + r * 5 + c] = s;
            }
#pragma unroll
        for (int r = 0; r < 5; r++)
#pragma unroll
            for (int k = 0; k < 5; k++) V[r * 5 + k] = -2.0f * b[k * 5 + r];
#pragma unroll
        for (int r = 0; r < 5; r++)
#pragma unroll
            for (int c = 0; c < 5; c++) {
                float s = 0.f;
#pragma unroll
                for (int k = 0; k < 5; k++) s += b[r * 5 + k] * b[c * 5 + k];
                V[25 + r * 5 + c] = s;
            }
#pragma unroll
        for (int k = 50; k < K1; k++) { U[k] = 0.f; V[k] = 0.f; }
    }
}

// ---------------------------------------------------------------------------
// Triangular tile decode: t -> (by, bx), by >= bx
// ---------------------------------------------------------------------------
__device__ __forceinline__ void tri_decode(int t, int& by, int& bx) {
    float f = sqrtf(8.0f * (float)t + 1.0f);
    int r = (int)((f - 1.0f) * 0.5f);
    while ((r + 1) * (r + 2) / 2 <= t) r++;
    while (r * (r + 1) / 2 > t) r--;
    by = r;
    bx = t - r * (r + 1) / 2;
}

// ---------------------------------------------------------------------------
// Pair body: 64x64 tile GEMM-style, each thread a 4x4 micro-tile.
// Returns this thread's partial loss sum.
// ---------------------------------------------------------------------------
template <int LAYER>
__device__ __forceinline__ float pair_body(int t, float* smem) {
    constexpr int D  = LAYER ? 5 : 3;
    constexpr int K  = LAYER ? K1 : K0;
    constexpr int K4 = K / 4;
    const float* __restrict__ gU = LAYER ? g_U1 : g_U0;
    const float* __restrict__ gV = LAYER ? g_V1 : g_V0;

    int by, bx;
    tri_decode(t, by, bx);
    int i0 = by * 64, j0 = bx * 64;
    int tid = threadIdx.x;

    float* Us = smem;            // [K][64] K-major
    float* Vs = smem + K * 64;   // [K][64]

    const float4* gU4 = (const float4*)gU;
    const float4* gV4 = (const float4*)gV;
    for (int e = tid; e < 64 * K4; e += 256) {
        int row = e / K4, k4 = e - row * K4;
        float4 u = gU4[(i0 + row) * K4 + k4];
        Us[(4 * k4 + 0) * 64 + row] = u.x;
        Us[(4 * k4 + 1) * 64 + row] = u.y;
        Us[(4 * k4 + 2) * 64 + row] = u.z;
        Us[(4 * k4 + 3) * 64 + row] = u.w;
        float4 v = gV4[(j0 + row) * K4 + k4];
        Vs[(4 * k4 + 0) * 64 + row] = v.x;
        Vs[(4 * k4 + 1) * 64 + row] = v.y;
        Vs[(4 * k4 + 2) * 64 + row] = v.z;
        Vs[(4 * k4 + 3) * 64 + row] = v.w;
    }
    __syncthreads();

    int tx = tid & 15, ty = tid >> 4;

    float acc[16];
#pragma unroll
    for (int q = 0; q < 16; q++) acc[q] = 0.f;

#pragma unroll 4
    for (int k = 0; k < K; k++) {
        float4 a = *(const float4*)&Us[k * 64 + ty * 4];
        float4 b = *(const float4*)&Vs[k * 64 + tx * 4];
        acc[0]  = fmaf(a.x, b.x, acc[0]);
        acc[1]  = fmaf(a.x, b.y, acc[1]);
        acc[2]  = fmaf(a.x, b.z, acc[2]);
        acc[3]  = fmaf(a.x, b.w, acc[3]);
        acc[4]  = fmaf(a.y, b.x, acc[4]);
        acc[5]  = fmaf(a.y, b.y, acc[5]);
        acc[6]  = fmaf(a.y, b.z, acc[6]);
        acc[7]  = fmaf(a.y, b.w, acc[7]);
        acc[8]  = fmaf(a.z, b.x, acc[8]);
        acc[9]  = fmaf(a.z, b.y, acc[9]);
        acc[10] = fmaf(a.z, b.z, acc[10]);
        acc[11] = fmaf(a.z, b.w, acc[11]);
        acc[12] = fmaf(a.w, b.x, acc[12]);
        acc[13] = fmaf(a.w, b.y, acc[13]);
        acc[14] = fmaf(a.w, b.z, acc[14]);
        acc[15] = fmaf(a.w, b.w, acc[15]);
    }

    float val = 0.f;
#pragma unroll
    for (int r = 0; r < 4; r++)
#pragma unroll
        for (int c = 0; c < 4; c++) {
            int i = i0 + ty * 4 + r;
            int j = j0 + tx * 4 + c;
            float d2 = fmaxf((float)D + acc[r * 4 + c], 0.0f);
            float e  = sqrtf(d2);
            float lv = fmaxf(0.0f, 1.0f - e);
            val += (i > j) ? lv : 0.0f;
        }
    return val;
}

// ---------------------------------------------------------------------------
// Combined pair kernel (layer1 blocks first: heavier K) + in-kernel finalize.
// ---------------------------------------------------------------------------
__global__ __launch_bounds__(256) void pair_all_kernel(float* __restrict__ out) {
    __shared__ float smem[2 * K1 * 64];   // 26 KB (max of both layers)

    int b = blockIdx.x;
    float val;
    bool layer1 = (b < NTRI1);
    if (layer1) val = pair_body<1>(b, smem);
    else        val = pair_body<0>(b - NTRI1, smem);

#pragma unroll
    for (int o = 16; o > 0; o >>= 1)
        val += __shfl_down_sync(0xffffffffu, val, o);

    __syncthreads();   // smem reads complete before reuse
    int tid = threadIdx.x;
    if ((tid & 31) == 0) smem[tid >> 5] = val;
    __syncthreads();

    if (tid == 0) {
        float s = 0.0f;
#pragma unroll
        for (int w = 0; w < 8; w++) s += smem[w];
        if (s != 0.0f)
            atomicAdd(layer1 ? &g_acc1 : &g_acc0, (double)s);
        __threadfence();
        unsigned done = atomicAdd(&g_count, 1u) + 1u;
        if (done == (unsigned)GRID_PAIR) {
            double a0 = atomicAdd(&g_acc0, 0.0);   // coherent read
            double a1 = atomicAdd(&g_acc1, 0.0);
            double l0 = 2.0 * a0 / ((double)N0 * (double)(N0 - 1));
            double l1 = 2.0 * a1 / ((double)N1 * (double)(N1 - 1));
            out[0] = (float)(0.5 * (l0 + l1));
        }
    }
}

extern "C" void kernel_launch(void* const* d_in, const int* in_sizes, int n_in,
                              void* d_out, int out_size) {
    const float* k0 = (const float*)d_in[0];
    const float* k1 = (const float*)d_in[1];
    float* out = (float*)d_out;

    prep_kernel<<<12, 256>>>(k0, k1);
    pair_all_kernel<<<GRID_PAIR, 256>>>(out);
}

// round 4
// speedup vs baseline: 2.6471x; 1.5062x over previous
#include <cuda_runtime.h>
#include <math.h>

#define N0 2048
#define N1 1024
#define K0 20               // 9 (A) + 9 (G) + 2 pad
#define K1 52               // 25 (A) + 25 (G) + 2 pad
// Tiles: 64 rows x 128 cols, thread micro-tile 4x8 (256 threads)
#define NBY0 (N0 / 64)      // 32
#define NBX0 (N0 / 128)     // 16
#define NBY1 (N1 / 64)      // 16
#define NBX1 (N1 / 128)     // 8
#define NTILE0 272          // sum_{bx=0..15} (32-2bx)
#define NTILE1 72           // sum_{bx=0..7}  (16-2bx)
#define GRID_ALL (NTILE0 + NTILE1)   // 344
#define NCHUNK 96           // 64 layer0 chunks + 32 layer1 chunks (32 matrices each)

// Scratch (allocation-free rule: __device__ globals, explicit zero-init)
// U row = [A(=inv) row-major, G=A^T A, pad]; V row = [-2*B^T, H=B B^T, pad]
// diff^2(i,j) = D + dot(U[i], V[j])
__device__ float    g_U0[N0 * K0];
__device__ float    g_V0[N0 * K0];
__device__ float    g_U1[N1 * K1];
__device__ float    g_V1[N1 * K1];
__device__ double   g_acc0 = 0.0;
__device__ double   g_acc1 = 0.0;
__device__ unsigned g_count = 0u;
__device__ int      g_flag[NCHUNK] = {};

typedef unsigned long long ull;

__device__ __forceinline__ ull pack_dup(float x) {
    ull r;
    asm("mov.b64 %0, {%1, %1};" : "=l"(r) : "f"(x));
    return r;
}
__device__ __forceinline__ void ffma2(ull& d, ull a, ull b) {
    asm("fma.rn.f32x2 %0, %1, %2, %0;" : "+l"(d) : "l"(a), "l"(b));
}
__device__ __forceinline__ float2 unpack2(ull v) {
    float2 f;
    asm("mov.b64 {%0, %1}, %2;" : "=f"(f.x), "=f"(f.y) : "l"(v));
    return f;
}

// ---------------------------------------------------------------------------
// Prep one layer-0 (3x3) matrix -> U/V rows
// ---------------------------------------------------------------------------
__device__ __forceinline__ void prep3(const float* __restrict__ in0, int i) {
    float a[9];
    float ss = 0.f;
#pragma unroll
    for (int k = 0; k < 9; k++) { a[k] = in0[i * 9 + k]; ss += a[k] * a[k]; }
    float inv_n = 1.0f / (sqrtf(ss) + 1e-8f);
#pragma unroll
    for (int k = 0; k < 9; k++) a[k] *= inv_n;

    float c00 = a[4] * a[8] - a[5] * a[7];
    float c01 = a[5] * a[6] - a[3] * a[8];
    float c02 = a[3] * a[7] - a[4] * a[6];
    float det = a[0] * c00 + a[1] * c01 + a[2] * c02;
    float id  = 1.0f / det;

    float v[9];
    v[0] = c00 * id;
    v[1] = (a[2] * a[7] - a[1] * a[8]) * id;
    v[2] = (a[1] * a[5] - a[2] * a[4]) * id;
    v[3] = c01 * id;
    v[4] = (a[0] * a[8] - a[2] * a[6]) * id;
    v[5] = (a[2] * a[3] - a[0] * a[5]) * id;
    v[6] = c02 * id;
    v[7] = (a[1] * a[6] - a[0] * a[7]) * id;
    v[8] = (a[0] * a[4] - a[1] * a[3]) * id;

    float* U = &g_U0[i * K0];
    float* V = &g_V0[i * K0];
#pragma unroll
    for (int k = 0; k < 9; k++) U[k] = v[k];
#pragma unroll
    for (int r = 0; r < 3; r++)
#pragma unroll
        for (int c = 0; c < 3; c++) {
            float s = 0.f;
#pragma unroll
            for (int k = 0; k < 3; k++) s += v[k * 3 + r] * v[k * 3 + c];
            U[9 + r * 3 + c] = s;
        }
#pragma unroll
    for (int r = 0; r < 3; r++)
#pragma unroll
        for (int k = 0; k < 3; k++) V[r * 3 + k] = -2.0f * a[k * 3 + r];
#pragma unroll
    for (int r = 0; r < 3; r++)
#pragma unroll
        for (int c = 0; c < 3; c++) {
            float s = 0.f;
#pragma unroll
            for (int k = 0; k < 3; k++) s += a[r * 3 + k] * a[c * 3 + k];
            V[9 + r * 3 + c] = s;
        }
#pragma unroll
    for (int k = 18; k < K0; k++) { U[k] = 0.f; V[k] = 0.f; }
}

// ---------------------------------------------------------------------------
// Prep one layer-1 (5x5) matrix: pivoted Gauss-Jordan, all static indices
// ---------------------------------------------------------------------------
__device__ __forceinline__ void prep5(const float* __restrict__ in1, int i) {
    float m[5][10];
    float b[25];
    float ss = 0.f;
#pragma unroll
    for (int r = 0; r < 5; r++)
#pragma unroll
        for (int c = 0; c < 5; c++) {
            float x = in1[i * 25 + r * 5 + c];
            m[r][c] = x; ss += x * x;
            m[r][c + 5] = (r == c) ? 1.0f : 0.0f;
        }
    float inv_n = 1.0f / (sqrtf(ss) + 1e-8f);
#pragma unroll
    for (int r = 0; r < 5; r++)
#pragma unroll
        for (int c = 0; c < 5; c++) { m[r][c] *= inv_n; b[r * 5 + c] = m[r][c]; }

#pragma unroll
    for (int col = 0; col < 5; col++) {
#pragma unroll
        for (int r2 = 0; r2 < 5; r2++) {
            if (r2 > col) {
                bool sw = fabsf(m[r2][col]) > fabsf(m[col][col]);
#pragma unroll
                for (int c = 0; c < 10; c++) {
                    float x = m[col][c], y = m[r2][c];
                    m[col][c] = sw ? y : x;
                    m[r2][c]  = sw ? x : y;
                }
            }
        }
        float piv = 1.0f / m[col][col];
#pragma unroll
        for (int c = 0; c < 10; c++) m[col][c] *= piv;
#pragma unroll
        for (int r = 0; r < 5; r++) {
            if (r == col) continue;
            float f = m[r][col];
#pragma unroll
            for (int c = 0; c < 10; c++) m[r][c] = fmaf(-f, m[col][c], m[r][c]);
        }
    }

    float v[25];
#pragma unroll
    for (int r = 0; r < 5; r++)
#pragma unroll
        for (int c = 0; c < 5; c++) v[r * 5 + c] = m[r][c + 5];

    float* U = &g_U1[i * K1];
    float* V = &g_V1[i * K1];
#pragma unroll
    for (int k = 0; k < 25; k++) U[k] = v[k];
#pragma unroll
    for (int r = 0; r < 5; r++)
#pragma unroll
        for (int c = 0; c < 5; c++) {
            float s = 0.f;
#pragma unroll
            for (int k = 0; k < 5; k++) s += v[k * 5 + r] * v[k * 5 + c];
            U[25 + r * 5 + c] = s;
        }
#pragma unroll
    for (int r = 0; r < 5; r++)
#pragma unroll
        for (int k = 0; k < 5; k++) V[r * 5 + k] = -2.0f * b[k * 5 + r];
#pragma unroll
    for (int r = 0; r < 5; r++)
#pragma unroll
        for (int c = 0; c < 5; c++) {
            float s = 0.f;
#pragma unroll
            for (int k = 0; k < 5; k++) s += b[r * 5 + k] * b[c * 5 + k];
            V[25 + r * 5 + c] = s;
        }
#pragma unroll
    for (int k = 50; k < K1; k++) { U[k] = 0.f; V[k] = 0.f; }
}

// ---------------------------------------------------------------------------
// Pair tile body: 64x128 tile, micro-tile 4x8 per thread, FFMA2 inner loop.
// ---------------------------------------------------------------------------
template <int LAYER>
__device__ __forceinline__ float tile_body(int t, float* smem, int tid) {
    constexpr int D   = LAYER ? 5 : 3;
    constexpr int K   = LAYER ? K1 : K0;
    constexpr int K4  = K / 4;
    constexpr int NBY = LAYER ? NBY1 : NBY0;
    constexpr int NBX = LAYER ? NBX1 : NBX0;
    constexpr int FB  = LAYER ? 64 : 0;   // flag base
    const float* __restrict__ gU = LAYER ? g_U1 : g_U0;
    const float* __restrict__ gV = LAYER ? g_V1 : g_V0;

    // trapezoid decode: tiles (by, bx) with by >= 2*bx; C(bx) = bx*(NBY+1-bx)
    int bx = 0;
    while (bx + 1 < NBX && (bx + 1) * (NBY + 1 - (bx + 1)) <= t) bx++;
    int by = 2 * bx + (t - bx * (NBY + 1 - bx));
    int i0 = by * 64, j0 = bx * 128;

    // spin on readiness of the 6 input chunks (32 matrices each)
    if (tid == 0) {
        int fl[6] = { FB + 2 * by, FB + 2 * by + 1,
                      FB + 4 * bx, FB + 4 * bx + 1, FB + 4 * bx + 2, FB + 4 * bx + 3 };
#pragma unroll
        for (int q = 0; q < 6; q++)
            while (atomicAdd(&g_flag[fl[q]], 0) == 0) __nanosleep(64);
    }
    __syncthreads();
    __threadfence();   // acquire producers' U/V writes

    float* Us = smem;             // [K][64]  k-major
    float* Vs = smem + K * 64;    // [K][128] k-major

    const float4* gU4 = (const float4*)gU;
    const float4* gV4 = (const float4*)gV;
    for (int e = tid; e < 64 * K4; e += 256) {
        int row = e / K4, k4 = e - row * K4;
        float4 u = gU4[(i0 + row) * K4 + k4];
        Us[(4 * k4 + 0) * 64 + row] = u.x;
        Us[(4 * k4 + 1) * 64 + row] = u.y;
        Us[(4 * k4 + 2) * 64 + row] = u.z;
        Us[(4 * k4 + 3) * 64 + row] = u.w;
    }
    for (int e = tid; e < 128 * K4; e += 256) {
        int row = e / K4, k4 = e - row * K4;
        float4 v = gV4[(j0 + row) * K4 + k4];
        Vs[(4 * k4 + 0) * 128 + row] = v.x;
        Vs[(4 * k4 + 1) * 128 + row] = v.y;
        Vs[(4 * k4 + 2) * 128 + row] = v.z;
        Vs[(4 * k4 + 3) * 128 + row] = v.w;
    }
    __syncthreads();

    int tx = tid & 15, ty = tid >> 4;
    const float* Urow = Us + ty * 4;
    const float* Vrow = Vs + tx * 8;

    ull acc[16];
#pragma unroll
    for (int q = 0; q < 16; q++) acc[q] = 0ull;

#pragma unroll 4
    for (int k = 0; k < K; k++) {
        float4 a = *(const float4*)(Urow + k * 64);
        ulonglong2 bA = *(const ulonglong2*)(Vrow + k * 128);       // cols (0,1),(2,3)
        ulonglong2 bB = *(const ulonglong2*)(Vrow + k * 128 + 4);   // cols (4,5),(6,7)
        ull a0 = pack_dup(a.x), a1 = pack_dup(a.y), a2 = pack_dup(a.z), a3 = pack_dup(a.w);
        ffma2(acc[0],  a0, bA.x); ffma2(acc[1],  a0, bA.y); ffma2(acc[2],  a0, bB.x); ffma2(acc[3],  a0, bB.y);
        ffma2(acc[4],  a1, bA.x); ffma2(acc[5],  a1, bA.y); ffma2(acc[6],  a1, bB.x); ffma2(acc[7],  a1, bB.y);
        ffma2(acc[8],  a2, bA.x); ffma2(acc[9],  a2, bA.y); ffma2(acc[10], a2, bB.x); ffma2(acc[11], a2, bB.y);
        ffma2(acc[12], a3, bA.x); ffma2(acc[13], a3, bA.y); ffma2(acc[14], a3, bB.x); ffma2(acc[15], a3, bB.y);
    }

    float val = 0.f;
    int ib = i0 + ty * 4, jb = j0 + tx * 8;
#pragma unroll
    for (int r = 0; r < 4; r++)
#pragma unroll
        for (int cp = 0; cp < 4; cp++) {
            float2 f = unpack2(acc[r * 4 + cp]);
            int i = ib + r;
            {
                float e = sqrtf(fmaxf((float)D + f.x, 0.0f));
                float lv = fmaxf(0.0f, 1.0f - e);
                if (i > jb + 2 * cp) val += lv;
            }
            {
                float e = sqrtf(fmaxf((float)D + f.y, 0.0f));
                float lv = fmaxf(0.0f, 1.0f - e);
                if (i > jb + 2 * cp + 1) val += lv;
            }
        }
    return val;
}

// ---------------------------------------------------------------------------
// Fused kernel: prep (blocks 0..95) + flagged pair tiles + finalize/self-clean
// ---------------------------------------------------------------------------
__global__ __launch_bounds__(256) void fused_kernel(const float* __restrict__ in0,
                                                    const float* __restrict__ in1,
                                                    float* __restrict__ out) {
    __shared__ float smem[K1 * 64 + K1 * 128];   // 39.9 KB, max layer
    int tid = threadIdx.x;
    int b = blockIdx.x;

    // ---- prep phase: first 96 blocks, one warp each, 32 matrices ----
    if (b < NCHUNK) {
        if (tid < 32) {
            if (b < 64) prep3(in0, b * 32 + tid);
            else        prep5(in1, (b - 64) * 32 + tid);
        }
        __syncthreads();
        if (tid == 0) {
            __threadfence();              // publish U/V before flag
            atomicExch(&g_flag[b], 1);
        }
    }

    // ---- pair phase ----
    bool layer1 = (b < NTILE1);
    float val = layer1 ? tile_body<1>(b, smem, tid)
                       : tile_body<0>(b - NTILE1, smem, tid);

#pragma unroll
    for (int o = 16; o > 0; o >>= 1)
        val += __shfl_down_sync(0xffffffffu, val, o);

    __syncthreads();   // smem main-loop reads done before reuse
    if ((tid & 31) == 0) smem[tid >> 5] = val;
    __syncthreads();

    if (tid == 0) {
        float s = 0.0f;
#pragma unroll
        for (int w = 0; w < 8; w++) s += smem[w];
        if (s != 0.0f)
            atomicAdd(layer1 ? &g_acc1 : &g_acc0, (double)s);
        __threadfence();
        unsigned done = atomicAdd(&g_count, 1u) + 1u;
        if (done == (unsigned)GRID_ALL) {
            double a0 = atomicAdd(&g_acc0, 0.0);
            double a1 = atomicAdd(&g_acc1, 0.0);
            double l0 = 2.0 * a0 / ((double)N0 * (double)(N0 - 1));
            double l1 = 2.0 * a1 / ((double)N1 * (double)(N1 - 1));
            out[0] = (float)(0.5 * (l0 + l1));
            // self-clean for the next graph replay (zero-invariant at entry)
            for (int q = 0; q < NCHUNK; q++) g_flag[q] = 0;
            g_acc0 = 0.0; g_acc1 = 0.0;
            __threadfence();
            g_count = 0u;
        }
    }
}

extern "C" void kernel_launch(void* const* d_in, const int* in_sizes, int n_in,
                              void* d_out, int out_size) {
    const float* k0 = (const float*)d_in[0];
    const float* k1 = (const float*)d_in[1];
    float* out = (float*)d_out;
    fused_kernel<<<GRID_ALL, 256>>>(k0, k1, out);
}